// round 10
// baseline (speedup 1.0000x reference)
#include <cuda_runtime.h>
#include <cooperative_groups.h>
#include <math.h>

namespace cg = cooperative_groups;

#define BB 64
#define MM 2048
#define CC 64
#define HH 128
#define NNZE 32768
#define H3 384
#define PADN 40960

// -------- scratch (static device arrays; no runtime malloc) --------
__device__ int           g_cluscnt[BB*CC];
__device__ int           g_clusoff[BB*CC];
__device__ int           g_csplit[BB*CC*4];
__device__ unsigned char g_nit[BB*MM];
__device__ int2          g_csr[BB*PADN];
__device__ float         g_xdec[BB*CC*H3];

// ============ K1: build cluster-ordered padded CSR (one CTA / graph) =====
__global__ void __launch_bounds__(1024) k_prep(const int* __restrict__ rows,
                                               const int* __restrict__ cols,
                                               const float* __restrict__ vals,
                                               const int* __restrict__ idx) {
    __shared__ int   hist[MM];
    __shared__ int   cur[MM];
    __shared__ int   ss[1024];
    __shared__ short pos2row[MM];
    __shared__ int   chist[CC], ccur[CC], coffs[CC];
    int g = blockIdx.x, tid = threadIdx.x;
    hist[tid] = 0; hist[tid + 1024] = 0;
    if (tid < CC) chist[tid] = 0;
    __syncthreads();

    const int* r  = rows + g * NNZE;
    const int* ix = idx  + g * MM;
    for (int i = tid; i < NNZE; i += 1024) atomicAdd(&hist[r[i]], 1);
    int i0 = ix[tid], i1 = ix[tid + 1024];
    atomicAdd(&chist[i0], 1);
    atomicAdd(&chist[i1], 1);
    __syncthreads();

    if (tid == 0) {
        int acc = 0;
        for (int c = 0; c < CC; c++) {
            coffs[c] = acc; ccur[c] = acc;
            g_clusoff[g*CC + c] = acc;
            g_cluscnt[g*CC + c] = chist[c];
            acc += chist[c];
        }
    }
    __syncthreads();

    int p0 = atomicAdd(&ccur[i0], 1); pos2row[p0] = (short)tid;
    int p1 = atomicAdd(&ccur[i1], 1); pos2row[p1] = (short)(tid + 1024);
    __syncthreads();

    int r0 = pos2row[2*tid], r1 = pos2row[2*tid + 1];
    int len0 = hist[r0], len1 = hist[r1];
    int l0 = (len0 + 3) & ~3, l1 = (len1 + 3) & ~3;
    int t = l0 + l1;
    ss[tid] = t;
    __syncthreads();
    for (int off = 1; off < 1024; off <<= 1) {
        int v = (tid >= off) ? ss[tid - off] : 0;
        __syncthreads();
        ss[tid] += v;
        __syncthreads();
    }
    int excl = ss[tid] - t;
    int o0 = excl, o1 = excl + l0;
    cur[r0] = o0;  cur[r1] = o1;
    g_nit[g*MM + 2*tid]     = (unsigned char)(l0 >> 2);
    g_nit[g*MM + 2*tid + 1] = (unsigned char)(l1 >> 2);

    int2* cbase = g_csr + (size_t)g * PADN;
    for (int k = len0; k < l0; k++) cbase[o0 + k] = make_int2(0, 0);
    for (int k = len1; k < l1; k++) cbase[o1 + k] = make_int2(0, 0);
    __syncthreads();

    if (tid < CC) {
        int cp = coffs[tid], nr = chist[tid];
        #pragma unroll
        for (int q = 0; q < 4; q++) {
            int qs = (nr * q) >> 2;
            g_csplit[(g*CC + tid)*4 + q] =
                (nr > 0) ? cur[pos2row[cp + qs]] : 0;
        }
    }
    __syncthreads();

    const int*   c = cols + g * NNZE;
    const float* v = vals + g * NNZE;
    for (int i = tid; i < NNZE; i += 1024) {
        int rr = r[i];
        int p = atomicAdd(&cur[rr], 1);
        cbase[p] = make_int2(c[i], __float_as_int(v[i]));
    }
}

// ============ K2: SpMM + pooling (round-7 fp32; at the L2 traffic floor) ==
__global__ void __launch_bounds__(256) k_spmm(const float4* __restrict__ x4) {
    __shared__ float comb[2][3][32][8];
    int g = blockIdx.x >> 5;
    int cgrp = blockIdx.x & 31;
    int wid = threadIdx.x >> 5, lane = threadIdx.x & 31;
    int ci = wid >> 2;
    int sub = wid & 3;
    int c = cgrp * 2 + ci;
    int nr  = g_cluscnt[g*CC + c];
    int pos = g_clusoff[g*CC + c];
    int lo = (nr * sub) >> 2, hi = (nr * (sub + 1)) >> 2;
    int eptr = g_csplit[(g*CC + c)*4 + sub];
    const float4* xq = x4 + (size_t)g * MM * 32;
    const int4* cs = (const int4*)(g_csr + (size_t)g * PADN + eptr);
    const unsigned char* nitp = g_nit + g * MM + pos;

    float4 s  = make_float4(0.f, 0.f, 0.f, 0.f);
    float4 mx = make_float4(-INFINITY, -INFINITY, -INFINITY, -INFINITY);

    for (int j0 = lo; j0 < hi; j0 += 32) {
        int lim = min(32, hi - j0);
        int myv = (lane < lim) ? (int)nitp[j0 + lane] : 0;
        for (int j = 0; j < lim; j++) {
            int it = __shfl_sync(0xFFFFFFFFu, myv, j);
            float4 acc = make_float4(0.f, 0.f, 0.f, 0.f);
            #pragma unroll 2
            for (int t = 0; t < it; t++) {
                int4 a = __ldg(cs);
                int4 b = __ldg(cs + 1);
                cs += 2;
                float4 v0 = __ldg(&xq[a.x * 32 + lane]);
                float4 v1 = __ldg(&xq[a.z * 32 + lane]);
                float4 v2 = __ldg(&xq[b.x * 32 + lane]);
                float4 v3 = __ldg(&xq[b.z * 32 + lane]);
                float f0 = __int_as_float(a.y), f1 = __int_as_float(a.w);
                float f2 = __int_as_float(b.y), f3 = __int_as_float(b.w);
                acc.x += f0*v0.x + f1*v1.x + f2*v2.x + f3*v3.x;
                acc.y += f0*v0.y + f1*v1.y + f2*v2.y + f3*v3.y;
                acc.z += f0*v0.z + f1*v1.z + f2*v2.z + f3*v3.z;
                acc.w += f0*v0.w + f1*v1.w + f2*v2.w + f3*v3.w;
            }
            s.x += acc.x; s.y += acc.y; s.z += acc.z; s.w += acc.w;
            mx.x = fmaxf(mx.x, acc.x); mx.y = fmaxf(mx.y, acc.y);
            mx.z = fmaxf(mx.z, acc.z); mx.w = fmaxf(mx.w, acc.w);
        }
    }
    if (sub != 0) {
        float* cb = comb[ci][sub - 1][lane];
        cb[0] = s.x;  cb[1] = s.y;  cb[2] = s.z;  cb[3] = s.w;
        cb[4] = mx.x; cb[5] = mx.y; cb[6] = mx.z; cb[7] = mx.w;
    }
    __syncthreads();
    if (sub == 0) {
        #pragma unroll
        for (int w = 0; w < 3; w++) {
            const float* cb = comb[ci][w][lane];
            s.x += cb[0]; s.y += cb[1]; s.z += cb[2]; s.w += cb[3];
            mx.x = fmaxf(mx.x, cb[4]); mx.y = fmaxf(mx.y, cb[5]);
            mx.z = fmaxf(mx.z, cb[6]); mx.w = fmaxf(mx.w, cb[7]);
        }
        float cf = fmaxf((float)nr, 1.f);
        float* xd = g_xdec + (g*CC + c) * H3;
        float4 mean = make_float4(s.x/cf, s.y/cf, s.z/cf, s.w/cf);
        *(float4*)&xd[lane*4]        = mean;
        *(float4*)&xd[HH + lane*4]   = mx;
        *(float4*)&xd[2*HH + lane*4] = s;
    }
}

// ============ packed f32x2 helpers ============
__device__ __forceinline__ void ffma2(unsigned long long& d,
                                      unsigned long long a,
                                      unsigned long long b) {
    asm("fma.rn.f32x2 %0, %1, %2, %0;" : "+l"(d) : "l"(a), "l"(b));
}
__device__ __forceinline__ unsigned long long pack2(float v) {
    unsigned long long r;
    asm("mov.b64 %0, {%1, %1};" : "=l"(r) : "f"(v));
    return r;
}

// ============ K3: fused QKV-GEMM + attention, cluster pair per graph =====
// Cluster (2 CTAs) = one graph. rank0 computes K full + Q rows [0:32);
// rank1 computes V full + Q rows [32:64). K/V exchanged via DSMEM copy;
// attention per CTA on its 32 Q-rows, everything smem-resident.
#define XSP_LD 66          // ulls per k-slice row-vector (pad)
#define KV_LD  140         // floats per Q/K/V row (35 float4, conflict-free)
#define SS_LD  65          // floats per S row (conflict-free)
#define NKT    12          // K tiles of 32 over H3=384

__global__ void __launch_bounds__(512, 1) __cluster_dims__(2, 1, 1)
k_fused(const float* __restrict__ Wq, const float* __restrict__ Wk,
        const float* __restrict__ Wv, float* __restrict__ out) {
    extern __shared__ char smraw[];
    unsigned long long* xsP = (unsigned long long*)smraw;        // 32*66 ull (16.9KB)
    float* ws2    = (float*)(smraw + 32*XSP_LD*8);               // 32*256 (32.8KB)
    float* Qs     = ws2 + 32*256;                                // 32*140 (17.9KB)
    float* KVown  = Qs + 32*KV_LD;                               // 64*140 (35.8KB)
    float* KVpeer = KVown + 64*KV_LD;                            // 64*140 (35.8KB)
    float* Ss     = KVpeer + 64*KV_LD;                           // 32*65  (8.3KB)

    int g = blockIdx.x >> 1;
    int rank = blockIdx.x & 1;
    int tid = threadIdx.x;
    int rg = tid & 31;          // KV row-pair id; Q local row; attn row
    int cgc = tid >> 5;         // col group 0..15 -> cols cgc*8..+7

    const float* xd = g_xdec + g * CC * H3;
    const float* Wsel = rank ? Wv : Wk;

    unsigned long long ak[2][4];
    unsigned long long aq[4];
    #pragma unroll
    for (int i = 0; i < 4; i++) { ak[0][i] = 0ull; ak[1][i] = 0ull; aq[i] = 0ull; }

    for (int kt = 0; kt < NKT; kt++) {
        __syncthreads();
        // stage xsP[kk][row] pre-packed (dup f32x2); coalesced gmem reads
        for (int i = tid; i < 32 * 64; i += 512) {
            int kk = i & 31, row = i >> 5;
            xsP[kk * XSP_LD + row] = pack2(xd[row * H3 + kt * 32 + kk]);
        }
        // stage W tiles: Wsel -> ws2[kk][0:128), Wq -> ws2[kk][128:256)
        for (int i = tid; i < 32 * 32; i += 512) {
            int row = i >> 5, c4 = i & 31;
            *(float4*)&ws2[row * 256 + c4 * 4] =
                __ldg((const float4*)&Wsel[(kt * 32 + row) * HH + c4 * 4]);
            *(float4*)&ws2[row * 256 + 128 + c4 * 4] =
                __ldg((const float4*)&Wq[(kt * 32 + row) * HH + c4 * 4]);
        }
        __syncthreads();
        #pragma unroll 4
        for (int kk = 0; kk < 32; kk++) {
            ulonglong2 pa = *(const ulonglong2*)&xsP[kk * XSP_LD + 2 * rg];
            unsigned long long paq = xsP[kk * XSP_LD + rank * 32 + rg];
            const float* wb = &ws2[kk * 256 + cgc * 8];
            ulonglong2 b01 = *(const ulonglong2*)wb;
            ulonglong2 b23 = *(const ulonglong2*)(wb + 4);
            ulonglong2 q01 = *(const ulonglong2*)(wb + 128);
            ulonglong2 q23 = *(const ulonglong2*)(wb + 132);
            ffma2(ak[0][0], pa.x, b01.x); ffma2(ak[0][1], pa.x, b01.y);
            ffma2(ak[0][2], pa.x, b23.x); ffma2(ak[0][3], pa.x, b23.y);
            ffma2(ak[1][0], pa.y, b01.x); ffma2(ak[1][1], pa.y, b01.y);
            ffma2(ak[1][2], pa.y, b23.x); ffma2(ak[1][3], pa.y, b23.y);
            ffma2(aq[0], paq, q01.x); ffma2(aq[1], paq, q01.y);
            ffma2(aq[2], paq, q23.x); ffma2(aq[3], paq, q23.y);
        }
    }
    // write own K-or-V tile and Q half to smem (regions untouched above)
    {
        float* r0 = &KVown[(2 * rg) * KV_LD + cgc * 8];
        float* r1 = &KVown[(2 * rg + 1) * KV_LD + cgc * 8];
        ulonglong2 t;
        t.x = ak[0][0]; t.y = ak[0][1]; *(ulonglong2*)r0 = t;
        t.x = ak[0][2]; t.y = ak[0][3]; *(ulonglong2*)(r0 + 4) = t;
        t.x = ak[1][0]; t.y = ak[1][1]; *(ulonglong2*)r1 = t;
        t.x = ak[1][2]; t.y = ak[1][3]; *(ulonglong2*)(r1 + 4) = t;
        float* qr = &Qs[rg * KV_LD + cgc * 8];
        t.x = aq[0]; t.y = aq[1]; *(ulonglong2*)qr = t;
        t.x = aq[2]; t.y = aq[3]; *(ulonglong2*)(qr + 4) = t;
    }
    cg::cluster_group cl = cg::this_cluster();
    cl.sync();
    // pull peer's K-or-V tile over DSMEM
    {
        const float4* psrc = (const float4*)cl.map_shared_rank((void*)KVown, rank ^ 1);
        float4* pdst = (float4*)KVpeer;
        for (int i = tid; i < 64 * (KV_LD / 4); i += 512) pdst[i] = psrc[i];
    }
    cl.sync();   // peer must finish reading our KVown before we may exit early
    const float* Ks = rank ? KVpeer : KVown;
    const float* Vs = rank ? KVown : KVpeer;

    // ---- S = Q K^T * scale : thread = (row rg, 4 cols at cgc*4)
    {
        float sacc[4] = {0.f, 0.f, 0.f, 0.f};
        const float4* q4 = (const float4*)Qs + rg * (KV_LD / 4);
        const float4* k4 = (const float4*)Ks;
        #pragma unroll 4
        for (int h4 = 0; h4 < 32; h4++) {
            float4 q = q4[h4];
            #pragma unroll
            for (int cc = 0; cc < 4; cc++) {
                float4 k = k4[(cgc * 4 + cc) * (KV_LD / 4) + h4];
                sacc[cc] += q.x*k.x + q.y*k.y + q.z*k.z + q.w*k.w;
            }
        }
        const float scale = 0.08838834764831845f;   // 1/sqrt(128)
        #pragma unroll
        for (int cc = 0; cc < 4; cc++)
            Ss[rg * SS_LD + cgc * 4 + cc] = sacc[cc] * scale;
    }
    __syncthreads();
    // warp-parallel softmax: 16 warps x 2 rows
    {
        int wid = tid >> 5, lane = tid & 31;
        int rr = wid * 2 + (lane >> 4);
        int l16 = lane & 15;
        float v0 = Ss[rr*SS_LD + l16];
        float v1 = Ss[rr*SS_LD + l16 + 16];
        float v2 = Ss[rr*SS_LD + l16 + 32];
        float v3 = Ss[rr*SS_LD + l16 + 48];
        float m = fmaxf(fmaxf(v0, v1), fmaxf(v2, v3));
        #pragma unroll
        for (int o = 1; o < 16; o <<= 1)
            m = fmaxf(m, __shfl_xor_sync(0xFFFFFFFFu, m, o));
        float e0 = __expf(v0 - m), e1 = __expf(v1 - m);
        float e2 = __expf(v2 - m), e3 = __expf(v3 - m);
        float sum = e0 + e1 + e2 + e3;
        #pragma unroll
        for (int o = 1; o < 16; o <<= 1)
            sum += __shfl_xor_sync(0xFFFFFFFFu, sum, o);
        float inv = 1.f / sum;
        Ss[rr*SS_LD + l16]      = e0 * inv;
        Ss[rr*SS_LD + l16 + 16] = e1 * inv;
        Ss[rr*SS_LD + l16 + 32] = e2 * inv;
        Ss[rr*SS_LD + l16 + 48] = e3 * inv;
    }
    __syncthreads();
    // ---- O = P V : thread = (row rg, 8 out cols at cgc*8)
    {
        float4 a0 = make_float4(0.f,0.f,0.f,0.f), a1 = a0;
        const float4* v4 = (const float4*)Vs;
        #pragma unroll 4
        for (int c = 0; c < CC; c++) {
            float p = Ss[rg * SS_LD + c];
            float4 v0 = v4[c * (KV_LD/4) + cgc * 2];
            float4 v1 = v4[c * (KV_LD/4) + cgc * 2 + 1];
            a0.x += p*v0.x; a0.y += p*v0.y; a0.z += p*v0.z; a0.w += p*v0.w;
            a1.x += p*v1.x; a1.y += p*v1.y; a1.z += p*v1.z; a1.w += p*v1.w;
        }
        float4* o4 = (float4*)out + g * 2048 + (rank * 32 + rg) * 32 + cgc * 2;
        o4[0] = a0; o4[1] = a1;
    }
}

extern "C" void kernel_launch(void* const* d_in, const int* in_sizes, int n_in,
                              void* d_out, int out_size) {
    const float* x    = (const float*)d_in[0];
    const int*   rows = (const int*)d_in[3];
    const int*   cols = (const int*)d_in[4];
    const float* vals = (const float*)d_in[5];
    const int*   idx  = (const int*)d_in[6];
    const float* Wq   = (const float*)d_in[7];
    const float* Wk   = (const float*)d_in[8];
    const float* Wv   = (const float*)d_in[9];
    float* out = (float*)d_out;

    static const int FUSED_SMEM =
        32*XSP_LD*8 + 32*256*4 + 32*KV_LD*4 + 2*64*KV_LD*4 + 32*SS_LD*4; // 147584 B
    cudaFuncSetAttribute(k_fused, cudaFuncAttributeMaxDynamicSharedMemorySize,
                         FUSED_SMEM);

    k_prep<<<BB, 1024>>>(rows, cols, vals, idx);
    k_spmm<<<BB * 32, 256>>>((const float4*)x);
    k_fused<<<BB * 2, 512, FUSED_SMEM>>>(Wq, Wk, Wv, out);
}

// round 12
// speedup vs baseline: 1.0888x; 1.0888x over previous
#include <cuda_runtime.h>
#include <math.h>

#define BB 64
#define MM 2048
#define CC 64
#define HH 128
#define NNZE 32768
#define H3 384
#define PADN 40960

// -------- scratch (static device arrays; no runtime malloc) --------
__device__ int           g_cluscnt[BB*CC];
__device__ int           g_clusoff[BB*CC];
__device__ int           g_csplit[BB*CC*4];
__device__ unsigned char g_nit[BB*MM];
__device__ int2          g_csr[BB*PADN];
__device__ float         g_xdec[BB*CC*H3];
__device__ float         g_qkv[2][3][BB*CC*HH];   // [K-half][Q/K/V]

// ============ K1: build cluster-ordered padded CSR (one CTA / graph) =====
__global__ void __launch_bounds__(1024) k_prep(const int* __restrict__ rows,
                                               const int* __restrict__ cols,
                                               const float* __restrict__ vals,
                                               const int* __restrict__ idx) {
    __shared__ int   hist[MM];
    __shared__ int   cur[MM];
    __shared__ int   ss[1024];
    __shared__ short pos2row[MM];
    __shared__ int   chist[CC], ccur[CC], coffs[CC];
    int g = blockIdx.x, tid = threadIdx.x;
    hist[tid] = 0; hist[tid + 1024] = 0;
    if (tid < CC) chist[tid] = 0;
    __syncthreads();

    const int* r  = rows + g * NNZE;
    const int* ix = idx  + g * MM;
    // histogram, loads batched 4-wide (MLP)
    for (int i = tid; i < NNZE; i += 4096) {
        int r0 = __ldg(&r[i]);
        int r1 = __ldg(&r[i + 1024]);
        int r2 = __ldg(&r[i + 2048]);
        int r3 = __ldg(&r[i + 3072]);
        atomicAdd(&hist[r0], 1);
        atomicAdd(&hist[r1], 1);
        atomicAdd(&hist[r2], 1);
        atomicAdd(&hist[r3], 1);
    }
    int i0 = __ldg(&ix[tid]), i1 = __ldg(&ix[tid + 1024]);
    atomicAdd(&chist[i0], 1);
    atomicAdd(&chist[i1], 1);
    __syncthreads();

    if (tid == 0) {
        int acc = 0;
        for (int c = 0; c < CC; c++) {
            coffs[c] = acc; ccur[c] = acc;
            g_clusoff[g*CC + c] = acc;
            g_cluscnt[g*CC + c] = chist[c];
            acc += chist[c];
        }
    }
    __syncthreads();

    int p0 = atomicAdd(&ccur[i0], 1); pos2row[p0] = (short)tid;
    int p1 = atomicAdd(&ccur[i1], 1); pos2row[p1] = (short)(tid + 1024);
    __syncthreads();

    int r0 = pos2row[2*tid], r1 = pos2row[2*tid + 1];
    int len0 = hist[r0], len1 = hist[r1];
    int l0 = (len0 + 3) & ~3, l1 = (len1 + 3) & ~3;
    int t = l0 + l1;
    ss[tid] = t;
    __syncthreads();
    for (int off = 1; off < 1024; off <<= 1) {
        int v = (tid >= off) ? ss[tid - off] : 0;
        __syncthreads();
        ss[tid] += v;
        __syncthreads();
    }
    int excl = ss[tid] - t;
    int o0 = excl, o1 = excl + l0;
    cur[r0] = o0;  cur[r1] = o1;
    g_nit[g*MM + 2*tid]     = (unsigned char)(l0 >> 2);
    g_nit[g*MM + 2*tid + 1] = (unsigned char)(l1 >> 2);

    int2* cbase = g_csr + (size_t)g * PADN;
    for (int k = len0; k < l0; k++) cbase[o0 + k] = make_int2(0, 0);
    for (int k = len1; k < l1; k++) cbase[o1 + k] = make_int2(0, 0);
    __syncthreads();

    if (tid < CC) {
        int cp = coffs[tid], nr = chist[tid];
        #pragma unroll
        for (int q = 0; q < 4; q++) {
            int qs = (nr * q) >> 2;
            g_csplit[(g*CC + tid)*4 + q] =
                (nr > 0) ? cur[pos2row[cp + qs]] : 0;
        }
    }
    __syncthreads();

    // scatter, loads batched 4-wide ahead of the dependent atomics
    const int*   c = cols + g * NNZE;
    const float* v = vals + g * NNZE;
    for (int i = tid; i < NNZE; i += 4096) {
        int   ra = __ldg(&r[i]),        rb = __ldg(&r[i + 1024]);
        int   rc = __ldg(&r[i + 2048]), rd = __ldg(&r[i + 3072]);
        int   ca = __ldg(&c[i]),        cb = __ldg(&c[i + 1024]);
        int   cc2 = __ldg(&c[i + 2048]), cd = __ldg(&c[i + 3072]);
        float va = __ldg(&v[i]),        vb = __ldg(&v[i + 1024]);
        float vc = __ldg(&v[i + 2048]), vd = __ldg(&v[i + 3072]);
        int pa = atomicAdd(&cur[ra], 1);
        int pb = atomicAdd(&cur[rb], 1);
        int pc = atomicAdd(&cur[rc], 1);
        int pd = atomicAdd(&cur[rd], 1);
        cbase[pa] = make_int2(ca, __float_as_int(va));
        cbase[pb] = make_int2(cb, __float_as_int(vb));
        cbase[pc] = make_int2(cc2, __float_as_int(vc));
        cbase[pd] = make_int2(cd, __float_as_int(vd));
    }
}

// ============ K2: SpMM + pooling (round-7 fp32; at the L2 traffic floor) ==
__global__ void __launch_bounds__(256) k_spmm(const float4* __restrict__ x4) {
    __shared__ float comb[2][3][32][8];
    int g = blockIdx.x >> 5;
    int cgrp = blockIdx.x & 31;
    int wid = threadIdx.x >> 5, lane = threadIdx.x & 31;
    int ci = wid >> 2;
    int sub = wid & 3;
    int c = cgrp * 2 + ci;
    int nr  = g_cluscnt[g*CC + c];
    int pos = g_clusoff[g*CC + c];
    int lo = (nr * sub) >> 2, hi = (nr * (sub + 1)) >> 2;
    int eptr = g_csplit[(g*CC + c)*4 + sub];
    const float4* xq = x4 + (size_t)g * MM * 32;
    const int4* cs = (const int4*)(g_csr + (size_t)g * PADN + eptr);
    const unsigned char* nitp = g_nit + g * MM + pos;

    float4 s  = make_float4(0.f, 0.f, 0.f, 0.f);
    float4 mx = make_float4(-INFINITY, -INFINITY, -INFINITY, -INFINITY);

    for (int j0 = lo; j0 < hi; j0 += 32) {
        int lim = min(32, hi - j0);
        int myv = (lane < lim) ? (int)nitp[j0 + lane] : 0;
        for (int j = 0; j < lim; j++) {
            int it = __shfl_sync(0xFFFFFFFFu, myv, j);
            float4 acc = make_float4(0.f, 0.f, 0.f, 0.f);
            #pragma unroll 2
            for (int t = 0; t < it; t++) {
                int4 a = __ldg(cs);
                int4 b = __ldg(cs + 1);
                cs += 2;
                float4 v0 = __ldg(&xq[a.x * 32 + lane]);
                float4 v1 = __ldg(&xq[a.z * 32 + lane]);
                float4 v2 = __ldg(&xq[b.x * 32 + lane]);
                float4 v3 = __ldg(&xq[b.z * 32 + lane]);
                float f0 = __int_as_float(a.y), f1 = __int_as_float(a.w);
                float f2 = __int_as_float(b.y), f3 = __int_as_float(b.w);
                acc.x += f0*v0.x + f1*v1.x + f2*v2.x + f3*v3.x;
                acc.y += f0*v0.y + f1*v1.y + f2*v2.y + f3*v3.y;
                acc.z += f0*v0.z + f1*v1.z + f2*v2.z + f3*v3.z;
                acc.w += f0*v0.w + f1*v1.w + f2*v2.w + f3*v3.w;
            }
            s.x += acc.x; s.y += acc.y; s.z += acc.z; s.w += acc.w;
            mx.x = fmaxf(mx.x, acc.x); mx.y = fmaxf(mx.y, acc.y);
            mx.z = fmaxf(mx.z, acc.z); mx.w = fmaxf(mx.w, acc.w);
        }
    }
    if (sub != 0) {
        float* cb = comb[ci][sub - 1][lane];
        cb[0] = s.x;  cb[1] = s.y;  cb[2] = s.z;  cb[3] = s.w;
        cb[4] = mx.x; cb[5] = mx.y; cb[6] = mx.z; cb[7] = mx.w;
    }
    __syncthreads();
    if (sub == 0) {
        #pragma unroll
        for (int w = 0; w < 3; w++) {
            const float* cb = comb[ci][w][lane];
            s.x += cb[0]; s.y += cb[1]; s.z += cb[2]; s.w += cb[3];
            mx.x = fmaxf(mx.x, cb[4]); mx.y = fmaxf(mx.y, cb[5]);
            mx.z = fmaxf(mx.z, cb[6]); mx.w = fmaxf(mx.w, cb[7]);
        }
        float cf = fmaxf((float)nr, 1.f);
        float* xd = g_xdec + (g*CC + c) * H3;
        float4 mean = make_float4(s.x/cf, s.y/cf, s.z/cf, s.w/cf);
        *(float4*)&xd[lane*4]        = mean;
        *(float4*)&xd[HH + lane*4]   = mx;
        *(float4*)&xd[2*HH + lane*4] = s;
    }
}

// ============ packed f32x2 helpers ============
__device__ __forceinline__ void ffma2(unsigned long long& d,
                                      unsigned long long a,
                                      unsigned long long b) {
    asm("fma.rn.f32x2 %0, %1, %2, %0;" : "+l"(d) : "l"(a), "l"(b));
}
__device__ __forceinline__ unsigned long long pack2(float v) {
    unsigned long long r;
    asm("mov.b64 %0, {%1, %1};" : "=l"(r) : "f"(v));
    return r;
}

// ============ K3: Q/K/V = x_dec @ W, grid (64, 3, 2Khalf x 2Nhalf) =======
// K-split raises occupancy (768 CTAs) WITHOUT doubling A staging. A is
// pre-packed f32x2 in smem: inner loop = 3 LDS.128 + 8 FFMA2, no MOVs.
// A_LD is EVEN so every ulonglong2 access is 16B-aligned (odd stride
// trapped with misaligned-address in round 11).
#define A_LD 66   // ull stride per k-slice (even => LDS.128-aligned)
__global__ void __launch_bounds__(256) k_gemm(const float* __restrict__ Wq,
                                              const float* __restrict__ Wk,
                                              const float* __restrict__ Wv) {
    extern __shared__ char smraw[];
    unsigned long long* As = (unsigned long long*)smraw;   // [64 kk][66 pad] ull
    float* Bs = (float*)(smraw + 64 * A_LD * 8);           // [64 kk][64 col]
    int g = blockIdx.x, which = blockIdx.y;
    int kh = blockIdx.z >> 1, nh = blockIdx.z & 1;
    const float* W = ((which == 0) ? Wq : (which == 1) ? Wk : Wv) + nh * 64;
    float* out = g_qkv[kh][which] + g * CC * HH + nh * 64;
    const float* xd = g_xdec + g * CC * H3 + kh * 192;
    int tid = threadIdx.x;
    int ty = tid >> 4, tx = tid & 15;   // rows ty*4..+3, cols tx*4..+3

    unsigned long long acc[4][2];
    #pragma unroll
    for (int i = 0; i < 4; i++) { acc[i][0] = 0ull; acc[i][1] = 0ull; }

    for (int kt = 0; kt < 192; kt += 64) {
        __syncthreads();
        // A: coalesced LDG (consecutive tid -> consecutive kk), packed STS
        for (int i = tid; i < 64 * 64; i += 256) {
            int kk = i & 63, row = i >> 6;
            As[kk * A_LD + row] = pack2(xd[row * H3 + kt + kk]);
        }
        // B tile [64 kk][64 col]
        for (int i = tid; i < 64 * 16; i += 256) {
            int row = i >> 4, c4 = i & 15;
            *(float4*)&Bs[row * 64 + c4 * 4] =
                __ldg((const float4*)&W[(kh * 192 + kt + row) * HH + c4 * 4]);
        }
        __syncthreads();
        #pragma unroll 16
        for (int kk = 0; kk < 64; kk++) {
            ulonglong2 a01 = *(const ulonglong2*)&As[kk * A_LD + ty * 4];
            ulonglong2 a23 = *(const ulonglong2*)&As[kk * A_LD + ty * 4 + 2];
            ulonglong2 b   = *(const ulonglong2*)&Bs[kk * 64 + tx * 4];
            ffma2(acc[0][0], a01.x, b.x);  ffma2(acc[0][1], a01.x, b.y);
            ffma2(acc[1][0], a01.y, b.x);  ffma2(acc[1][1], a01.y, b.y);
            ffma2(acc[2][0], a23.x, b.x);  ffma2(acc[2][1], a23.x, b.y);
            ffma2(acc[3][0], a23.y, b.x);  ffma2(acc[3][1], a23.y, b.y);
        }
    }
    #pragma unroll
    for (int i = 0; i < 4; i++) {
        ulonglong2 o; o.x = acc[i][0]; o.y = acc[i][1];
        *(ulonglong2*)&out[(ty*4 + i) * HH + tx * 4] = o;
    }
}

// ============ K4: attention; staging sums the two K-half partials =========
__global__ void __launch_bounds__(256) k_attn(float* __restrict__ out) {
    extern __shared__ float sm[];
    float* Qs = sm;                   // 16 * 132
    float* Ks = Qs + 16 * 132;        // 64 * 132
    float* Vs = Ks + 64 * 132;        // 64 * 132
    float* Ss = Vs + 64 * 132;        // 16 * 68
    int g = blockIdx.x, rh = blockIdx.y * 16, tid = threadIdx.x;
    const float4* Qg0 = (const float4*)(g_qkv[0][0] + g * CC * HH + rh * HH);
    const float4* Qg1 = (const float4*)(g_qkv[1][0] + g * CC * HH + rh * HH);
    const float4* Kg0 = (const float4*)(g_qkv[0][1] + g * CC * HH);
    const float4* Kg1 = (const float4*)(g_qkv[1][1] + g * CC * HH);
    const float4* Vg0 = (const float4*)(g_qkv[0][2] + g * CC * HH);
    const float4* Vg1 = (const float4*)(g_qkv[1][2] + g * CC * HH);

    for (int i = tid; i < 16 * 32; i += 256) {
        int r = i >> 5, cc = i & 31;
        float4 a = __ldg(&Qg0[r * 32 + cc]);
        float4 b = __ldg(&Qg1[r * 32 + cc]);
        ((float4*)Qs)[r * 33 + cc] =
            make_float4(a.x+b.x, a.y+b.y, a.z+b.z, a.w+b.w);
    }
    for (int i = tid; i < 64 * 32; i += 256) {
        int r = i >> 5, cc = i & 31;
        float4 a = __ldg(&Kg0[r * 32 + cc]);
        float4 b = __ldg(&Kg1[r * 32 + cc]);
        ((float4*)Ks)[r * 33 + cc] =
            make_float4(a.x+b.x, a.y+b.y, a.z+b.z, a.w+b.w);
        float4 c = __ldg(&Vg0[r * 32 + cc]);
        float4 d = __ldg(&Vg1[r * 32 + cc]);
        ((float4*)Vs)[r * 33 + cc] =
            make_float4(c.x+d.x, c.y+d.y, c.z+d.z, c.w+d.w);
    }
    __syncthreads();

    int r = tid & 15, grp = tid >> 4;
    {
        float sacc[4] = {0.f, 0.f, 0.f, 0.f};
        const float4* q4 = (const float4*)Qs + r * 33;
        const float4* k4 = (const float4*)Ks;
        #pragma unroll 4
        for (int h4 = 0; h4 < 32; h4++) {
            float4 q = q4[h4];
            #pragma unroll
            for (int cc = 0; cc < 4; cc++) {
                float4 k = k4[(grp*4 + cc) * 33 + h4];
                sacc[cc] += q.x*k.x + q.y*k.y + q.z*k.z + q.w*k.w;
            }
        }
        const float scale = 0.08838834764831845f;   // 1/sqrt(128)
        #pragma unroll
        for (int cc = 0; cc < 4; cc++) Ss[r*68 + grp*4 + cc] = sacc[cc] * scale;
    }
    __syncthreads();
    {
        int wid = tid >> 5, lane = tid & 31;
        int rr = wid * 2 + (lane >> 4);
        int l16 = lane & 15;
        float v0 = Ss[rr*68 + l16];
        float v1 = Ss[rr*68 + l16 + 16];
        float v2 = Ss[rr*68 + l16 + 32];
        float v3 = Ss[rr*68 + l16 + 48];
        float m = fmaxf(fmaxf(v0, v1), fmaxf(v2, v3));
        #pragma unroll
        for (int o = 1; o < 16; o <<= 1)
            m = fmaxf(m, __shfl_xor_sync(0xFFFFFFFFu, m, o));
        float e0 = __expf(v0 - m), e1 = __expf(v1 - m);
        float e2 = __expf(v2 - m), e3 = __expf(v3 - m);
        float sum = e0 + e1 + e2 + e3;
        #pragma unroll
        for (int o = 1; o < 16; o <<= 1)
            sum += __shfl_xor_sync(0xFFFFFFFFu, sum, o);
        float inv = 1.f / sum;
        Ss[rr*68 + l16]      = e0 * inv;
        Ss[rr*68 + l16 + 16] = e1 * inv;
        Ss[rr*68 + l16 + 32] = e2 * inv;
        Ss[rr*68 + l16 + 48] = e3 * inv;
    }
    __syncthreads();
    {
        float4 a0 = make_float4(0.f,0.f,0.f,0.f), a1 = a0;
        const float4* v4 = (const float4*)Vs;
        #pragma unroll 4
        for (int c = 0; c < CC; c++) {
            float p = Ss[r*68 + c];
            float4 v0 = v4[c * 33 + grp * 2];
            float4 v1 = v4[c * 33 + grp * 2 + 1];
            a0.x += p*v0.x; a0.y += p*v0.y; a0.z += p*v0.z; a0.w += p*v0.w;
            a1.x += p*v1.x; a1.y += p*v1.y; a1.z += p*v1.z; a1.w += p*v1.w;
        }
        float4* o4 = (float4*)out + g * 2048 + (rh + r) * 32 + grp * 2;
        o4[0] = a0; o4[1] = a1;
    }
}

extern "C" void kernel_launch(void* const* d_in, const int* in_sizes, int n_in,
                              void* d_out, int out_size) {
    const float* x    = (const float*)d_in[0];
    const int*   rows = (const int*)d_in[3];
    const int*   cols = (const int*)d_in[4];
    const float* vals = (const float*)d_in[5];
    const int*   idx  = (const int*)d_in[6];
    const float* Wq   = (const float*)d_in[7];
    const float* Wk   = (const float*)d_in[8];
    const float* Wv   = (const float*)d_in[9];
    float* out = (float*)d_out;

    static const int GEMM_SMEM = 64*A_LD*8 + 64*64*4;               // 50176 B
    static const int ATTN_SMEM = ((16 + 2*64) * 132 + 16*68) * 4;   // 80384 B
    cudaFuncSetAttribute(k_gemm, cudaFuncAttributeMaxDynamicSharedMemorySize, GEMM_SMEM);
    cudaFuncSetAttribute(k_attn, cudaFuncAttributeMaxDynamicSharedMemorySize, ATTN_SMEM);

    k_prep<<<BB, 1024>>>(rows, cols, vals, idx);
    k_spmm<<<BB * 32, 256>>>((const float4*)x);
    k_gemm<<<dim3(BB, 3, 4), 256, GEMM_SMEM>>>(Wq, Wk, Wv);
    k_attn<<<dim3(BB, 4), 256, ATTN_SMEM>>>(out);
}

// round 13
// speedup vs baseline: 1.0970x; 1.0075x over previous
#include <cuda_runtime.h>
#include <math.h>

#define BB 64
#define MM 2048
#define CC 64
#define HH 128
#define NNZE 32768
#define H3 384
#define PADN 40960

// -------- scratch (static device arrays; no runtime malloc) --------
__device__ int           g_cluscnt[BB*CC];
__device__ int           g_clusoff[BB*CC];
__device__ int           g_csplit[BB*CC*4];
__device__ unsigned char g_nit[BB*MM];
__device__ int2          g_csr[BB*PADN];
__device__ float         g_xdec[BB*CC*H3];
__device__ float         g_Q[BB*CC*HH];
__device__ float         g_K[BB*CC*HH];
__device__ float         g_V[BB*CC*HH];

// ============ K1: build cluster-ordered padded CSR (one CTA / graph) =====
__global__ void __launch_bounds__(1024) k_prep(const int* __restrict__ rows,
                                               const int* __restrict__ cols,
                                               const float* __restrict__ vals,
                                               const int* __restrict__ idx) {
    __shared__ int   hist[MM];
    __shared__ int   cur[MM];
    __shared__ int   ss[1024];
    __shared__ short pos2row[MM];
    __shared__ int   chist[CC], ccur[CC], coffs[CC];
    int g = blockIdx.x, tid = threadIdx.x;
    hist[tid] = 0; hist[tid + 1024] = 0;
    if (tid < CC) chist[tid] = 0;
    __syncthreads();

    const int* r  = rows + g * NNZE;
    const int* ix = idx  + g * MM;
    for (int i = tid; i < NNZE; i += 1024) atomicAdd(&hist[r[i]], 1);
    int i0 = ix[tid], i1 = ix[tid + 1024];
    atomicAdd(&chist[i0], 1);
    atomicAdd(&chist[i1], 1);
    __syncthreads();

    if (tid == 0) {
        int acc = 0;
        for (int c = 0; c < CC; c++) {
            coffs[c] = acc; ccur[c] = acc;
            g_clusoff[g*CC + c] = acc;
            g_cluscnt[g*CC + c] = chist[c];
            acc += chist[c];
        }
    }
    __syncthreads();

    int p0 = atomicAdd(&ccur[i0], 1); pos2row[p0] = (short)tid;
    int p1 = atomicAdd(&ccur[i1], 1); pos2row[p1] = (short)(tid + 1024);
    __syncthreads();

    int r0 = pos2row[2*tid], r1 = pos2row[2*tid + 1];
    int len0 = hist[r0], len1 = hist[r1];
    int l0 = (len0 + 3) & ~3, l1 = (len1 + 3) & ~3;
    int t = l0 + l1;
    ss[tid] = t;
    __syncthreads();
    for (int off = 1; off < 1024; off <<= 1) {
        int v = (tid >= off) ? ss[tid - off] : 0;
        __syncthreads();
        ss[tid] += v;
        __syncthreads();
    }
    int excl = ss[tid] - t;
    int o0 = excl, o1 = excl + l0;
    cur[r0] = o0;  cur[r1] = o1;
    g_nit[g*MM + 2*tid]     = (unsigned char)(l0 >> 2);
    g_nit[g*MM + 2*tid + 1] = (unsigned char)(l1 >> 2);

    int2* cbase = g_csr + (size_t)g * PADN;
    for (int k = len0; k < l0; k++) cbase[o0 + k] = make_int2(0, 0);
    for (int k = len1; k < l1; k++) cbase[o1 + k] = make_int2(0, 0);
    __syncthreads();

    if (tid < CC) {
        int cp = coffs[tid], nr = chist[tid];
        #pragma unroll
        for (int q = 0; q < 4; q++) {
            int qs = (nr * q) >> 2;
            g_csplit[(g*CC + tid)*4 + q] =
                (nr > 0) ? cur[pos2row[cp + qs]] : 0;
        }
    }
    __syncthreads();

    const int*   c = cols + g * NNZE;
    const float* v = vals + g * NNZE;
    for (int i = tid; i < NNZE; i += 1024) {
        int rr = r[i];
        int p = atomicAdd(&cur[rr], 1);
        cbase[p] = make_int2(c[i], __float_as_int(v[i]));
    }
}

// ============ K2: SpMM + pooling (round-7 fp32; at the L2 traffic floor) ==
__global__ void __launch_bounds__(256) k_spmm(const float4* __restrict__ x4) {
    __shared__ float comb[2][3][32][8];
    int g = blockIdx.x >> 5;
    int cgrp = blockIdx.x & 31;
    int wid = threadIdx.x >> 5, lane = threadIdx.x & 31;
    int ci = wid >> 2;
    int sub = wid & 3;
    int c = cgrp * 2 + ci;
    int nr  = g_cluscnt[g*CC + c];
    int pos = g_clusoff[g*CC + c];
    int lo = (nr * sub) >> 2, hi = (nr * (sub + 1)) >> 2;
    int eptr = g_csplit[(g*CC + c)*4 + sub];
    const float4* xq = x4 + (size_t)g * MM * 32;
    const int4* cs = (const int4*)(g_csr + (size_t)g * PADN + eptr);
    const unsigned char* nitp = g_nit + g * MM + pos;

    float4 s  = make_float4(0.f, 0.f, 0.f, 0.f);
    float4 mx = make_float4(-INFINITY, -INFINITY, -INFINITY, -INFINITY);

    for (int j0 = lo; j0 < hi; j0 += 32) {
        int lim = min(32, hi - j0);
        int myv = (lane < lim) ? (int)nitp[j0 + lane] : 0;
        for (int j = 0; j < lim; j++) {
            int it = __shfl_sync(0xFFFFFFFFu, myv, j);
            float4 acc = make_float4(0.f, 0.f, 0.f, 0.f);
            #pragma unroll 2
            for (int t = 0; t < it; t++) {
                int4 a = __ldg(cs);
                int4 b = __ldg(cs + 1);
                cs += 2;
                float4 v0 = __ldg(&xq[a.x * 32 + lane]);
                float4 v1 = __ldg(&xq[a.z * 32 + lane]);
                float4 v2 = __ldg(&xq[b.x * 32 + lane]);
                float4 v3 = __ldg(&xq[b.z * 32 + lane]);
                float f0 = __int_as_float(a.y), f1 = __int_as_float(a.w);
                float f2 = __int_as_float(b.y), f3 = __int_as_float(b.w);
                acc.x += f0*v0.x + f1*v1.x + f2*v2.x + f3*v3.x;
                acc.y += f0*v0.y + f1*v1.y + f2*v2.y + f3*v3.y;
                acc.z += f0*v0.z + f1*v1.z + f2*v2.z + f3*v3.z;
                acc.w += f0*v0.w + f1*v1.w + f2*v2.w + f3*v3.w;
            }
            s.x += acc.x; s.y += acc.y; s.z += acc.z; s.w += acc.w;
            mx.x = fmaxf(mx.x, acc.x); mx.y = fmaxf(mx.y, acc.y);
            mx.z = fmaxf(mx.z, acc.z); mx.w = fmaxf(mx.w, acc.w);
        }
    }
    if (sub != 0) {
        float* cb = comb[ci][sub - 1][lane];
        cb[0] = s.x;  cb[1] = s.y;  cb[2] = s.z;  cb[3] = s.w;
        cb[4] = mx.x; cb[5] = mx.y; cb[6] = mx.z; cb[7] = mx.w;
    }
    __syncthreads();
    if (sub == 0) {
        #pragma unroll
        for (int w = 0; w < 3; w++) {
            const float* cb = comb[ci][w][lane];
            s.x += cb[0]; s.y += cb[1]; s.z += cb[2]; s.w += cb[3];
            mx.x = fmaxf(mx.x, cb[4]); mx.y = fmaxf(mx.y, cb[5]);
            mx.z = fmaxf(mx.z, cb[6]); mx.w = fmaxf(mx.w, cb[7]);
        }
        float cf = fmaxf((float)nr, 1.f);
        float* xd = g_xdec + (g*CC + c) * H3;
        float4 mean = make_float4(s.x/cf, s.y/cf, s.z/cf, s.w/cf);
        *(float4*)&xd[lane*4]        = mean;
        *(float4*)&xd[HH + lane*4]   = mx;
        *(float4*)&xd[2*HH + lane*4] = s;
    }
}

// ============ packed f32x2 helpers ============
__device__ __forceinline__ void ffma2(unsigned long long& d,
                                      unsigned long long a,
                                      unsigned long long b) {
    asm("fma.rn.f32x2 %0, %1, %2, %0;" : "+l"(d) : "l"(a), "l"(b));
}
__device__ __forceinline__ unsigned long long pack2(float v) {
    unsigned long long r;
    asm("mov.b64 %0, {%1, %1};" : "=l"(r) : "f"(v));
    return r;
}

// ============ K3: Q/K/V = x_dec @ W, grid (64, 3, 2 N-halves) ============
// R8 config (384 CTAs, single wave, no duplicated W traffic) + pre-packed
// f32x2 A in smem: inner loop = 3 LDS.128 + 8 FFMA2, zero pack-MOVs.
// A_LD EVEN so ulonglong2 accesses stay 16B-aligned.
#define A_LD 66   // ull stride per k-slice
__global__ void __launch_bounds__(256) k_gemm(const float* __restrict__ Wq,
                                              const float* __restrict__ Wk,
                                              const float* __restrict__ Wv) {
    extern __shared__ char smraw[];
    unsigned long long* As = (unsigned long long*)smraw;   // [64 kk][66] ull
    float* Bs = (float*)(smraw + 64 * A_LD * 8);           // [64 kk][64 col]
    int g = blockIdx.x, which = blockIdx.y, nh = blockIdx.z;
    const float* W = ((which == 0) ? Wq : (which == 1) ? Wk : Wv) + nh * 64;
    float* out = ((which == 0) ? g_Q : (which == 1) ? g_K : g_V)
                 + g * CC * HH + nh * 64;
    const float* xd = g_xdec + g * CC * H3;
    int tid = threadIdx.x;
    int ty = tid >> 4, tx = tid & 15;   // rows ty*4..+3, cols tx*4..+3

    unsigned long long acc[4][2];
    #pragma unroll
    for (int i = 0; i < 4; i++) { acc[i][0] = 0ull; acc[i][1] = 0ull; }

    for (int kt = 0; kt < H3; kt += 64) {
        __syncthreads();
        // A: coalesced LDG (consecutive tid -> consecutive kk), packed STS
        for (int i = tid; i < 64 * 64; i += 256) {
            int kk = i & 63, row = i >> 6;
            As[kk * A_LD + row] = pack2(xd[row * H3 + kt + kk]);
        }
        // B tile [64 kk][64 col]
        for (int i = tid; i < 64 * 16; i += 256) {
            int row = i >> 4, c4 = i & 15;
            *(float4*)&Bs[row * 64 + c4 * 4] =
                __ldg((const float4*)&W[(kt + row) * HH + c4 * 4]);
        }
        __syncthreads();
        #pragma unroll 8
        for (int kk = 0; kk < 64; kk++) {
            ulonglong2 a01 = *(const ulonglong2*)&As[kk * A_LD + ty * 4];
            ulonglong2 a23 = *(const ulonglong2*)&As[kk * A_LD + ty * 4 + 2];
            ulonglong2 b   = *(const ulonglong2*)&Bs[kk * 64 + tx * 4];
            ffma2(acc[0][0], a01.x, b.x);  ffma2(acc[0][1], a01.x, b.y);
            ffma2(acc[1][0], a01.y, b.x);  ffma2(acc[1][1], a01.y, b.y);
            ffma2(acc[2][0], a23.x, b.x);  ffma2(acc[2][1], a23.x, b.y);
            ffma2(acc[3][0], a23.y, b.x);  ffma2(acc[3][1], a23.y, b.y);
        }
    }
    #pragma unroll
    for (int i = 0; i < 4; i++) {
        ulonglong2 o; o.x = acc[i][0]; o.y = acc[i][1];
        *(ulonglong2*)&out[(ty*4 + i) * HH + tx * 4] = o;
    }
}

// ============ K4: attention (round-8 version; measured 15.6us) ===========
__global__ void __launch_bounds__(256) k_attn(float* __restrict__ out) {
    extern __shared__ float sm[];
    float* Qs = sm;                   // 16 * 132
    float* Ks = Qs + 16 * 132;        // 64 * 132
    float* Vs = Ks + 64 * 132;        // 64 * 132
    float* Ss = Vs + 64 * 132;        // 16 * 68
    int g = blockIdx.x, rh = blockIdx.y * 16, tid = threadIdx.x;
    const float4* Qg = (const float4*)(g_Q + g * CC * HH + rh * HH);
    const float4* Kg = (const float4*)(g_K + g * CC * HH);
    const float4* Vg = (const float4*)(g_V + g * CC * HH);

    for (int i = tid; i < 16 * 32; i += 256) {
        int r = i >> 5, cc = i & 31;
        ((float4*)Qs)[r * 33 + cc] = __ldg(&Qg[r * 32 + cc]);
    }
    for (int i = tid; i < 64 * 32; i += 256) {
        int r = i >> 5, cc = i & 31;
        ((float4*)Ks)[r * 33 + cc] = __ldg(&Kg[r * 32 + cc]);
        ((float4*)Vs)[r * 33 + cc] = __ldg(&Vg[r * 32 + cc]);
    }
    __syncthreads();

    int r = tid & 15, grp = tid >> 4;      // 16 rows x 16 col-groups
    {
        float sacc[4] = {0.f, 0.f, 0.f, 0.f};
        const float4* q4 = (const float4*)Qs + r * 33;
        const float4* k4 = (const float4*)Ks;
        #pragma unroll 4
        for (int h4 = 0; h4 < 32; h4++) {
            float4 q = q4[h4];
            #pragma unroll
            for (int cc = 0; cc < 4; cc++) {
                float4 k = k4[(grp*4 + cc) * 33 + h4];
                sacc[cc] += q.x*k.x + q.y*k.y + q.z*k.z + q.w*k.w;
            }
        }
        const float scale = 0.08838834764831845f;   // 1/sqrt(128)
        #pragma unroll
        for (int cc = 0; cc < 4; cc++) Ss[r*68 + grp*4 + cc] = sacc[cc] * scale;
    }
    __syncthreads();
    // warp-parallel softmax: 8 warps x 2 rows; 16 lanes per row, 4 cols/lane
    {
        int wid = tid >> 5, lane = tid & 31;
        int rr = wid * 2 + (lane >> 4);
        int l16 = lane & 15;
        float v0 = Ss[rr*68 + l16];
        float v1 = Ss[rr*68 + l16 + 16];
        float v2 = Ss[rr*68 + l16 + 32];
        float v3 = Ss[rr*68 + l16 + 48];
        float m = fmaxf(fmaxf(v0, v1), fmaxf(v2, v3));
        #pragma unroll
        for (int o = 1; o < 16; o <<= 1)
            m = fmaxf(m, __shfl_xor_sync(0xFFFFFFFFu, m, o));
        float e0 = __expf(v0 - m), e1 = __expf(v1 - m);
        float e2 = __expf(v2 - m), e3 = __expf(v3 - m);
        float sum = e0 + e1 + e2 + e3;
        #pragma unroll
        for (int o = 1; o < 16; o <<= 1)
            sum += __shfl_xor_sync(0xFFFFFFFFu, sum, o);
        float inv = 1.f / sum;
        Ss[rr*68 + l16]      = e0 * inv;
        Ss[rr*68 + l16 + 16] = e1 * inv;
        Ss[rr*68 + l16 + 32] = e2 * inv;
        Ss[rr*68 + l16 + 48] = e3 * inv;
    }
    __syncthreads();
    {
        float4 a0 = make_float4(0.f,0.f,0.f,0.f), a1 = a0;
        const float4* v4 = (const float4*)Vs;
        #pragma unroll 4
        for (int c = 0; c < CC; c++) {
            float p = Ss[r*68 + c];
            float4 v0 = v4[c * 33 + grp * 2];
            float4 v1 = v4[c * 33 + grp * 2 + 1];
            a0.x += p*v0.x; a0.y += p*v0.y; a0.z += p*v0.z; a0.w += p*v0.w;
            a1.x += p*v1.x; a1.y += p*v1.y; a1.z += p*v1.z; a1.w += p*v1.w;
        }
        float4* o4 = (float4*)out + g * 2048 + (rh + r) * 32 + grp * 2;
        o4[0] = a0; o4[1] = a1;
    }
}

extern "C" void kernel_launch(void* const* d_in, const int* in_sizes, int n_in,
                              void* d_out, int out_size) {
    const float* x    = (const float*)d_in[0];
    const int*   rows = (const int*)d_in[3];
    const int*   cols = (const int*)d_in[4];
    const float* vals = (const float*)d_in[5];
    const int*   idx  = (const int*)d_in[6];
    const float* Wq   = (const float*)d_in[7];
    const float* Wk   = (const float*)d_in[8];
    const float* Wv   = (const float*)d_in[9];
    float* out = (float*)d_out;

    static const int GEMM_SMEM = 64*A_LD*8 + 64*64*4;               // 50176 B
    static const int ATTN_SMEM = ((16 + 2*64) * 132 + 16*68) * 4;   // 80384 B
    cudaFuncSetAttribute(k_gemm, cudaFuncAttributeMaxDynamicSharedMemorySize, GEMM_SMEM);
    cudaFuncSetAttribute(k_attn, cudaFuncAttributeMaxDynamicSharedMemorySize, ATTN_SMEM);

    k_prep<<<BB, 1024>>>(rows, cols, vals, idx);
    k_spmm<<<BB * 32, 256>>>((const float4*)x);
    k_gemm<<<dim3(BB, 3, 2), 256, GEMM_SMEM>>>(Wq, Wk, Wv);
    k_attn<<<dim3(BB, 4), 256, ATTN_SMEM>>>(out);
}

// round 14
// speedup vs baseline: 1.0971x; 1.0002x over previous
#include <cuda_runtime.h>
#include <math.h>

#define BB 64
#define MM 2048
#define CC 64
#define HH 128
#define NNZE 32768
#define H3 384
#define PADN 40960

// -------- scratch (static device arrays; no runtime malloc) --------
__device__ int           g_cluscnt[BB*CC];
__device__ int           g_clusoff[BB*CC];
__device__ int           g_csplit[BB*CC*4];
__device__ unsigned char g_nit[BB*MM];
__device__ int2          g_csr[BB*PADN];
__device__ float         g_xdec[BB*CC*H3];
__device__ float         g_qkv3[3][3][BB*CC*HH];  // [K-third][Q/K/V]

// ============ K1: build cluster-ordered padded CSR (one CTA / graph) =====
__global__ void __launch_bounds__(1024) k_prep(const int* __restrict__ rows,
                                               const int* __restrict__ cols,
                                               const float* __restrict__ vals,
                                               const int* __restrict__ idx) {
    __shared__ int   hist[MM];
    __shared__ int   cur[MM];
    __shared__ int   ss[1024];
    __shared__ short pos2row[MM];
    __shared__ int   chist[CC], ccur[CC], coffs[CC];
    int g = blockIdx.x, tid = threadIdx.x;
    hist[tid] = 0; hist[tid + 1024] = 0;
    if (tid < CC) chist[tid] = 0;
    __syncthreads();

    const int* r  = rows + g * NNZE;
    const int* ix = idx  + g * MM;
    for (int i = tid; i < NNZE; i += 1024) atomicAdd(&hist[r[i]], 1);
    int i0 = ix[tid], i1 = ix[tid + 1024];
    atomicAdd(&chist[i0], 1);
    atomicAdd(&chist[i1], 1);
    __syncthreads();

    if (tid == 0) {
        int acc = 0;
        for (int c = 0; c < CC; c++) {
            coffs[c] = acc; ccur[c] = acc;
            g_clusoff[g*CC + c] = acc;
            g_cluscnt[g*CC + c] = chist[c];
            acc += chist[c];
        }
    }
    __syncthreads();

    int p0 = atomicAdd(&ccur[i0], 1); pos2row[p0] = (short)tid;
    int p1 = atomicAdd(&ccur[i1], 1); pos2row[p1] = (short)(tid + 1024);
    __syncthreads();

    int r0 = pos2row[2*tid], r1 = pos2row[2*tid + 1];
    int len0 = hist[r0], len1 = hist[r1];
    int l0 = (len0 + 3) & ~3, l1 = (len1 + 3) & ~3;
    int t = l0 + l1;
    ss[tid] = t;
    __syncthreads();
    for (int off = 1; off < 1024; off <<= 1) {
        int v = (tid >= off) ? ss[tid - off] : 0;
        __syncthreads();
        ss[tid] += v;
        __syncthreads();
    }
    int excl = ss[tid] - t;
    int o0 = excl, o1 = excl + l0;
    cur[r0] = o0;  cur[r1] = o1;
    g_nit[g*MM + 2*tid]     = (unsigned char)(l0 >> 2);
    g_nit[g*MM + 2*tid + 1] = (unsigned char)(l1 >> 2);

    int2* cbase = g_csr + (size_t)g * PADN;
    for (int k = len0; k < l0; k++) cbase[o0 + k] = make_int2(0, 0);
    for (int k = len1; k < l1; k++) cbase[o1 + k] = make_int2(0, 0);
    __syncthreads();

    if (tid < CC) {
        int cp = coffs[tid], nr = chist[tid];
        #pragma unroll
        for (int q = 0; q < 4; q++) {
            int qs = (nr * q) >> 2;
            g_csplit[(g*CC + tid)*4 + q] =
                (nr > 0) ? cur[pos2row[cp + qs]] : 0;
        }
    }
    __syncthreads();

    const int*   c = cols + g * NNZE;
    const float* v = vals + g * NNZE;
    for (int i = tid; i < NNZE; i += 1024) {
        int rr = r[i];
        int p = atomicAdd(&cur[rr], 1);
        cbase[p] = make_int2(c[i], __float_as_int(v[i]));
    }
}

// ============ K2: SpMM + pooling (round-7 fp32; at the L2 traffic floor) ==
__global__ void __launch_bounds__(256) k_spmm(const float4* __restrict__ x4) {
    __shared__ float comb[2][3][32][8];
    int g = blockIdx.x >> 5;
    int cgrp = blockIdx.x & 31;
    int wid = threadIdx.x >> 5, lane = threadIdx.x & 31;
    int ci = wid >> 2;
    int sub = wid & 3;
    int c = cgrp * 2 + ci;
    int nr  = g_cluscnt[g*CC + c];
    int pos = g_clusoff[g*CC + c];
    int lo = (nr * sub) >> 2, hi = (nr * (sub + 1)) >> 2;
    int eptr = g_csplit[(g*CC + c)*4 + sub];
    const float4* xq = x4 + (size_t)g * MM * 32;
    const int4* cs = (const int4*)(g_csr + (size_t)g * PADN + eptr);
    const unsigned char* nitp = g_nit + g * MM + pos;

    float4 s  = make_float4(0.f, 0.f, 0.f, 0.f);
    float4 mx = make_float4(-INFINITY, -INFINITY, -INFINITY, -INFINITY);

    for (int j0 = lo; j0 < hi; j0 += 32) {
        int lim = min(32, hi - j0);
        int myv = (lane < lim) ? (int)nitp[j0 + lane] : 0;
        for (int j = 0; j < lim; j++) {
            int it = __shfl_sync(0xFFFFFFFFu, myv, j);
            float4 acc = make_float4(0.f, 0.f, 0.f, 0.f);
            #pragma unroll 2
            for (int t = 0; t < it; t++) {
                int4 a = __ldg(cs);
                int4 b = __ldg(cs + 1);
                cs += 2;
                float4 v0 = __ldg(&xq[a.x * 32 + lane]);
                float4 v1 = __ldg(&xq[a.z * 32 + lane]);
                float4 v2 = __ldg(&xq[b.x * 32 + lane]);
                float4 v3 = __ldg(&xq[b.z * 32 + lane]);
                float f0 = __int_as_float(a.y), f1 = __int_as_float(a.w);
                float f2 = __int_as_float(b.y), f3 = __int_as_float(b.w);
                acc.x += f0*v0.x + f1*v1.x + f2*v2.x + f3*v3.x;
                acc.y += f0*v0.y + f1*v1.y + f2*v2.y + f3*v3.y;
                acc.z += f0*v0.z + f1*v1.z + f2*v2.z + f3*v3.z;
                acc.w += f0*v0.w + f1*v1.w + f2*v2.w + f3*v3.w;
            }
            s.x += acc.x; s.y += acc.y; s.z += acc.z; s.w += acc.w;
            mx.x = fmaxf(mx.x, acc.x); mx.y = fmaxf(mx.y, acc.y);
            mx.z = fmaxf(mx.z, acc.z); mx.w = fmaxf(mx.w, acc.w);
        }
    }
    if (sub != 0) {
        float* cb = comb[ci][sub - 1][lane];
        cb[0] = s.x;  cb[1] = s.y;  cb[2] = s.z;  cb[3] = s.w;
        cb[4] = mx.x; cb[5] = mx.y; cb[6] = mx.z; cb[7] = mx.w;
    }
    __syncthreads();
    if (sub == 0) {
        #pragma unroll
        for (int w = 0; w < 3; w++) {
            const float* cb = comb[ci][w][lane];
            s.x += cb[0]; s.y += cb[1]; s.z += cb[2]; s.w += cb[3];
            mx.x = fmaxf(mx.x, cb[4]); mx.y = fmaxf(mx.y, cb[5]);
            mx.z = fmaxf(mx.z, cb[6]); mx.w = fmaxf(mx.w, cb[7]);
        }
        float cf = fmaxf((float)nr, 1.f);
        float* xd = g_xdec + (g*CC + c) * H3;
        float4 mean = make_float4(s.x/cf, s.y/cf, s.z/cf, s.w/cf);
        *(float4*)&xd[lane*4]        = mean;
        *(float4*)&xd[HH + lane*4]   = mx;
        *(float4*)&xd[2*HH + lane*4] = s;
    }
}

// ============ packed f32x2 helpers ============
__device__ __forceinline__ void ffma2(unsigned long long& d,
                                      unsigned long long a,
                                      unsigned long long b) {
    asm("fma.rn.f32x2 %0, %1, %2, %0;" : "+l"(d) : "l"(a), "l"(b));
}
__device__ __forceinline__ unsigned long long pack2(float v) {
    unsigned long long r;
    asm("mov.b64 %0, {%1, %1};" : "=l"(r) : "f"(v));
    return r;
}

// ============ K3: Q/K/V = x_dec @ W, grid (64, 3, 3 K-thirds) ============
// 576 CTAs -> 3.9/SM, max 4: kills the 384-CTA wave quantization that held
// the fma pipe at ~60%. No staging duplication (each CTA owns a K-third of
// A and W). 4x8 microtile, pack-in-loop (pre-packed A measured worse).
#define XS_LD 68
__global__ void __launch_bounds__(256) k_gemm(const float* __restrict__ Wq,
                                              const float* __restrict__ Wk,
                                              const float* __restrict__ Wv) {
    extern __shared__ float sm[];
    float* xsA = sm;                 // [64 kk][68 pad] A^T tile (K-third slice)
    float* Bs  = sm + 64 * XS_LD;    // [64 kk][128 col] W tile
    int g = blockIdx.x, which = blockIdx.y, kh = blockIdx.z;
    const float* W = (which == 0) ? Wq : (which == 1) ? Wk : Wv;
    float* out = g_qkv3[kh][which] + g * CC * HH;
    const float* xd = g_xdec + g * CC * H3 + kh * 128;
    int tid = threadIdx.x;
    int ty = tid >> 4, tx = tid & 15;    // rows ty*4..+3, cols tx*8..+7

    unsigned long long acc[4][4];
    #pragma unroll
    for (int i = 0; i < 4; i++)
        #pragma unroll
        for (int j = 0; j < 4; j++) acc[i][j] = 0ull;

    for (int kt = 0; kt < 128; kt += 64) {
        __syncthreads();
        for (int i = tid; i < 64 * 64; i += 256) {
            int rr = i >> 6, kk = i & 63;
            xsA[kk * XS_LD + rr] = xd[rr * H3 + kt + kk];
        }
        for (int i = tid; i < 64 * 32; i += 256) {
            int row = i >> 5, c4 = i & 31;
            *(float4*)&Bs[row * HH + c4 * 4] =
                __ldg((const float4*)&W[(kh * 128 + kt + row) * HH + c4 * 4]);
        }
        __syncthreads();
        #pragma unroll 8
        for (int kk = 0; kk < 64; kk++) {
            float4 av = *(const float4*)&xsA[kk * XS_LD + ty * 4];
            const float* wb = &Bs[kk * HH + tx * 8];
            ulonglong2 b01 = *(const ulonglong2*)wb;
            ulonglong2 b23 = *(const ulonglong2*)(wb + 4);
            unsigned long long pa0 = pack2(av.x), pa1 = pack2(av.y);
            unsigned long long pa2 = pack2(av.z), pa3 = pack2(av.w);
            ffma2(acc[0][0], pa0, b01.x); ffma2(acc[0][1], pa0, b01.y);
            ffma2(acc[0][2], pa0, b23.x); ffma2(acc[0][3], pa0, b23.y);
            ffma2(acc[1][0], pa1, b01.x); ffma2(acc[1][1], pa1, b01.y);
            ffma2(acc[1][2], pa1, b23.x); ffma2(acc[1][3], pa1, b23.y);
            ffma2(acc[2][0], pa2, b01.x); ffma2(acc[2][1], pa2, b01.y);
            ffma2(acc[2][2], pa2, b23.x); ffma2(acc[2][3], pa2, b23.y);
            ffma2(acc[3][0], pa3, b01.x); ffma2(acc[3][1], pa3, b01.y);
            ffma2(acc[3][2], pa3, b23.x); ffma2(acc[3][3], pa3, b23.y);
        }
    }
    #pragma unroll
    for (int i = 0; i < 4; i++) {
        ulonglong2 o0; o0.x = acc[i][0]; o0.y = acc[i][1];
        ulonglong2 o1; o1.x = acc[i][2]; o1.y = acc[i][3];
        *(ulonglong2*)&out[(ty*4 + i) * HH + tx * 8]     = o0;
        *(ulonglong2*)&out[(ty*4 + i) * HH + tx * 8 + 4] = o1;
    }
}

// ============ K4: attention; staging sums the three K-third partials =====
__global__ void __launch_bounds__(256) k_attn(float* __restrict__ out) {
    extern __shared__ float sm[];
    float* Qs = sm;                   // 16 * 132
    float* Ks = Qs + 16 * 132;        // 64 * 132
    float* Vs = Ks + 64 * 132;        // 64 * 132
    float* Ss = Vs + 64 * 132;        // 16 * 68
    int g = blockIdx.x, rh = blockIdx.y * 16, tid = threadIdx.x;
    size_t qoff = (size_t)g * CC * HH + (size_t)rh * HH;
    size_t koff = (size_t)g * CC * HH;

    for (int i = tid; i < 16 * 32; i += 256) {
        int r = i >> 5, cc = i & 31;
        float4 a = __ldg((const float4*)(g_qkv3[0][0] + qoff) + r * 32 + cc);
        float4 b = __ldg((const float4*)(g_qkv3[1][0] + qoff) + r * 32 + cc);
        float4 c = __ldg((const float4*)(g_qkv3[2][0] + qoff) + r * 32 + cc);
        ((float4*)Qs)[r * 33 + cc] =
            make_float4(a.x+b.x+c.x, a.y+b.y+c.y, a.z+b.z+c.z, a.w+b.w+c.w);
    }
    for (int i = tid; i < 64 * 32; i += 256) {
        int r = i >> 5, cc = i & 31;
        float4 a = __ldg((const float4*)(g_qkv3[0][1] + koff) + r * 32 + cc);
        float4 b = __ldg((const float4*)(g_qkv3[1][1] + koff) + r * 32 + cc);
        float4 c = __ldg((const float4*)(g_qkv3[2][1] + koff) + r * 32 + cc);
        ((float4*)Ks)[r * 33 + cc] =
            make_float4(a.x+b.x+c.x, a.y+b.y+c.y, a.z+b.z+c.z, a.w+b.w+c.w);
        float4 d = __ldg((const float4*)(g_qkv3[0][2] + koff) + r * 32 + cc);
        float4 e = __ldg((const float4*)(g_qkv3[1][2] + koff) + r * 32 + cc);
        float4 f = __ldg((const float4*)(g_qkv3[2][2] + koff) + r * 32 + cc);
        ((float4*)Vs)[r * 33 + cc] =
            make_float4(d.x+e.x+f.x, d.y+e.y+f.y, d.z+e.z+f.z, d.w+e.w+f.w);
    }
    __syncthreads();

    int r = tid & 15, grp = tid >> 4;
    {
        float sacc[4] = {0.f, 0.f, 0.f, 0.f};
        const float4* q4 = (const float4*)Qs + r * 33;
        const float4* k4 = (const float4*)Ks;
        #pragma unroll 4
        for (int h4 = 0; h4 < 32; h4++) {
            float4 q = q4[h4];
            #pragma unroll
            for (int cc = 0; cc < 4; cc++) {
                float4 k = k4[(grp*4 + cc) * 33 + h4];
                sacc[cc] += q.x*k.x + q.y*k.y + q.z*k.z + q.w*k.w;
            }
        }
        const float scale = 0.08838834764831845f;   // 1/sqrt(128)
        #pragma unroll
        for (int cc = 0; cc < 4; cc++) Ss[r*68 + grp*4 + cc] = sacc[cc] * scale;
    }
    __syncthreads();
    {
        int wid = tid >> 5, lane = tid & 31;
        int rr = wid * 2 + (lane >> 4);
        int l16 = lane & 15;
        float v0 = Ss[rr*68 + l16];
        float v1 = Ss[rr*68 + l16 + 16];
        float v2 = Ss[rr*68 + l16 + 32];
        float v3 = Ss[rr*68 + l16 + 48];
        float m = fmaxf(fmaxf(v0, v1), fmaxf(v2, v3));
        #pragma unroll
        for (int o = 1; o < 16; o <<= 1)
            m = fmaxf(m, __shfl_xor_sync(0xFFFFFFFFu, m, o));
        float e0 = __expf(v0 - m), e1 = __expf(v1 - m);
        float e2 = __expf(v2 - m), e3 = __expf(v3 - m);
        float sum = e0 + e1 + e2 + e3;
        #pragma unroll
        for (int o = 1; o < 16; o <<= 1)
            sum += __shfl_xor_sync(0xFFFFFFFFu, sum, o);
        float inv = 1.f / sum;
        Ss[rr*68 + l16]      = e0 * inv;
        Ss[rr*68 + l16 + 16] = e1 * inv;
        Ss[rr*68 + l16 + 32] = e2 * inv;
        Ss[rr*68 + l16 + 48] = e3 * inv;
    }
    __syncthreads();
    {
        float4 a0 = make_float4(0.f,0.f,0.f,0.f), a1 = a0;
        const float4* v4 = (const float4*)Vs;
        #pragma unroll 4
        for (int c = 0; c < CC; c++) {
            float p = Ss[r*68 + c];
            float4 v0 = v4[c * 33 + grp * 2];
            float4 v1 = v4[c * 33 + grp * 2 + 1];
            a0.x += p*v0.x; a0.y += p*v0.y; a0.z += p*v0.z; a0.w += p*v0.w;
            a1.x += p*v1.x; a1.y += p*v1.y; a1.z += p*v1.z; a1.w += p*v1.w;
        }
        float4* o4 = (float4*)out + g * 2048 + (rh + r) * 32 + grp * 2;
        o4[0] = a0; o4[1] = a1;
    }
}

extern "C" void kernel_launch(void* const* d_in, const int* in_sizes, int n_in,
                              void* d_out, int out_size) {
    const float* x    = (const float*)d_in[0];
    const int*   rows = (const int*)d_in[3];
    const int*   cols = (const int*)d_in[4];
    const float* vals = (const float*)d_in[5];
    const int*   idx  = (const int*)d_in[6];
    const float* Wq   = (const float*)d_in[7];
    const float* Wk   = (const float*)d_in[8];
    const float* Wv   = (const float*)d_in[9];
    float* out = (float*)d_out;

    static const int GEMM_SMEM = (64*XS_LD + 64*HH) * 4;            // 50176 B
    static const int ATTN_SMEM = ((16 + 2*64) * 132 + 16*68) * 4;   // 80384 B
    cudaFuncSetAttribute(k_gemm, cudaFuncAttributeMaxDynamicSharedMemorySize, GEMM_SMEM);
    cudaFuncSetAttribute(k_attn, cudaFuncAttributeMaxDynamicSharedMemorySize, ATTN_SMEM);

    k_prep<<<BB, 1024>>>(rows, cols, vals, idx);
    k_spmm<<<BB * 32, 256>>>((const float4*)x);
    k_gemm<<<dim3(BB, 3, 3), 256, GEMM_SMEM>>>(Wq, Wk, Wv);
    k_attn<<<dim3(BB, 4), 256, ATTN_SMEM>>>(out);
}